// round 2
// baseline (speedup 1.0000x reference)
#include <cuda_runtime.h>

#define DIM   1024
#define CANDN 16384
#define SSZ   512
#define MSZ   4096
#define LSZ   8192
#define KPROM 128
#define PD    64
#define PAIR_CAP 65536
#define NLCHUNK 32
#define NVCHUNK 16
#define TB   128
#define LDP  68
#define SCREEN_T 0.979f
#define MERGE_T  0.98f

// ------------- scratch (device globals; no allocation) -------------
__device__ float g_norms[CANDN];
__device__ int   g_top[KPROM];
__device__ float g_lpart[NLCHUNK * DIM];
__device__ float g_mean[DIM];
__device__ float g_q[DIM];
__device__ float g_vpart[NVCHUNK * DIM];
__device__ float g_v[DIM];
__device__ float g_scores[SSZ];
__device__ float g_cand[DIM];
__device__ float g_candn2;
__device__ float g_mn2[MSZ];
__device__ float g_sims[MSZ];
__device__ float g_P[MSZ * PD];
__device__ float g_res[MSZ];
__device__ int   g_pairs[PAIR_CAP * 2];
__device__ int   g_npairs;
__device__ unsigned long long g_intmax;

// ------------- helpers -------------
__device__ __forceinline__ float dot4(float4 a, float4 b) {
    return a.x*b.x + a.y*b.y + a.z*b.z + a.w*b.w;
}
__device__ __forceinline__ float wsum(float v) {
#pragma unroll
    for (int o = 16; o; o >>= 1) v += __shfl_xor_sync(0xFFFFFFFFu, v, o);
    return v;
}
__device__ __forceinline__ unsigned ordf(float f) {
    unsigned u = __float_as_uint(f);
    return (u & 0x80000000u) ? ~u : (u | 0x80000000u);
}
__device__ __forceinline__ float deordf(unsigned u) {
    return (u & 0x80000000u) ? __uint_as_float(u & 0x7FFFFFFFu) : __uint_as_float(~u);
}
// block sum (all threads receive result); sbuf: float[32]
__device__ __forceinline__ float bsum(float v, float* sbuf) {
    int t = threadIdx.x, lane = t & 31, wid = t >> 5;
    v = wsum(v);
    if (!lane) sbuf[wid] = v;
    __syncthreads();
    int nw = blockDim.x >> 5;
    if (wid == 0) {
        float x = (lane < nw) ? sbuf[lane] : 0.f;
        x = wsum(x);
        if (!lane) sbuf[0] = x;
    }
    __syncthreads();
    v = sbuf[0];
    __syncthreads();
    return v;
}
// block argmax (desc value, asc index ties); all threads receive
__device__ __forceinline__ void bargmax(float& bv, int& bi, float* sv, int* si) {
    int t = threadIdx.x, lane = t & 31, wid = t >> 5;
#pragma unroll
    for (int o = 16; o; o >>= 1) {
        float ov = __shfl_xor_sync(0xFFFFFFFFu, bv, o);
        int   oi = __shfl_xor_sync(0xFFFFFFFFu, bi, o);
        if (ov > bv || (ov == bv && oi < bi)) { bv = ov; bi = oi; }
    }
    if (!lane) { sv[wid] = bv; si[wid] = bi; }
    __syncthreads();
    int nw = blockDim.x >> 5;
    if (wid == 0) {
        float xv = (lane < nw) ? sv[lane] : -3e38f;
        int   xi = (lane < nw) ? si[lane] : 0x7FFFFFFF;
#pragma unroll
        for (int o = 16; o; o >>= 1) {
            float ov = __shfl_xor_sync(0xFFFFFFFFu, xv, o);
            int   oi = __shfl_xor_sync(0xFFFFFFFFu, xi, o);
            if (ov > xv || (ov == xv && oi < xi)) { xv = ov; xi = oi; }
        }
        if (!lane) { sv[0] = xv; si[0] = xi; }
    }
    __syncthreads();
    bv = sv[0]; bi = si[0];
    __syncthreads();
}
__device__ __forceinline__ void bargmin(float& bv, int& bi, float* sv, int* si) {
    int t = threadIdx.x, lane = t & 31, wid = t >> 5;
#pragma unroll
    for (int o = 16; o; o >>= 1) {
        float ov = __shfl_xor_sync(0xFFFFFFFFu, bv, o);
        int   oi = __shfl_xor_sync(0xFFFFFFFFu, bi, o);
        if (ov < bv || (ov == bv && oi < bi)) { bv = ov; bi = oi; }
    }
    if (!lane) { sv[wid] = bv; si[wid] = bi; }
    __syncthreads();
    int nw = blockDim.x >> 5;
    if (wid == 0) {
        float xv = (lane < nw) ? sv[lane] : 3e38f;
        int   xi = (lane < nw) ? si[lane] : 0x7FFFFFFF;
#pragma unroll
        for (int o = 16; o; o >>= 1) {
            float ov = __shfl_xor_sync(0xFFFFFFFFu, xv, o);
            int   oi = __shfl_xor_sync(0xFFFFFFFFu, xi, o);
            if (ov < xv || (ov == xv && oi < xi)) { xv = ov; xi = oi; }
        }
        if (!lane) { sv[0] = xv; si[0] = xi; }
    }
    __syncthreads();
    bv = sv[0]; bi = si[0];
    __syncthreads();
}

// ------------- kernels -------------
__global__ void k_init() { g_npairs = 0; g_intmax = 0ull; }

__global__ void k_copy4(const float4* __restrict__ s, float4* __restrict__ d, int n) {
    int i = blockIdx.x * blockDim.x + threadIdx.x;
    if (i < n) d[i] = s[i];
}

// copy l_memory to out_l + partial column sums
__global__ void k_lmean1(const float* __restrict__ l, float* __restrict__ outl) {
    int c  = blockIdx.x * 256 + threadIdx.x;
    int r0 = blockIdx.y * (LSZ / NLCHUNK);
    float s = 0.f;
    for (int r = r0; r < r0 + (LSZ / NLCHUNK); r++) {
        float v = l[(size_t)r * DIM + c];
        outl[(size_t)r * DIM + c] = v;
        s += v;
    }
    g_lpart[blockIdx.y * DIM + c] = s;
}
__global__ void k_lmean2() {
    int c = threadIdx.x;
    float s = 0.f;
    for (int k = 0; k < NLCHUNK; k++) s += g_lpart[k * DIM + c];
    g_mean[c] = s / (float)LSZ;
}

__global__ void k_toknorm(const float* __restrict__ tok) {
    int w = (blockIdx.x * blockDim.x + threadIdx.x) >> 5;
    int lane = threadIdx.x & 31;
    const float4* p = (const float4*)(tok + (size_t)w * DIM);
    float s = 0.f;
#pragma unroll
    for (int k = 0; k < 8; k++) { float4 v = p[lane + 32 * k]; s += dot4(v, v); }
    s = wsum(s);
    if (!lane) g_norms[w] = s;
}

// single-block top-128 (value desc, index asc ties)
__global__ void k_topk() {
    __shared__ int   hist[256];
    __shared__ float sval[1024];
    __shared__ int   sidx[1024];
    __shared__ int   s_cnt, s_b1;
    __shared__ float wv[32]; __shared__ int wi[32];
    int t = threadIdx.x;
    if (t < 256) hist[t] = 0;
    __syncthreads();
    for (int i = t; i < CANDN; i += 1024)
        atomicAdd(&hist[ordf(g_norms[i]) >> 24], 1);
    __syncthreads();
    if (t == 0) {
        int c = 0, b = 255;
        for (; b > 0; b--) { if (c + hist[b] >= KPROM) break; c += hist[b]; }
        s_b1 = b; s_cnt = 0;
    }
    __syncthreads();
    int b1 = s_b1;
    for (int i = t; i < CANDN; i += 1024) {
        float v = g_norms[i];
        if ((int)(ordf(v) >> 24) >= b1) {
            int p = atomicAdd(&s_cnt, 1);
            if (p < 1024) { sval[p] = v; sidx[p] = i; }
        }
    }
    __syncthreads();
    int M = s_cnt;
    if (M <= 1024) {
        if (t < M) {
            float v = sval[t]; int id = sidx[t]; int r = 0;
            for (int f = 0; f < M; f++) {
                float vf = sval[f]; int idf = sidx[f];
                r += (vf > v) || (vf == v && idf < id);
            }
            if (r < KPROM) g_top[r] = id;
        }
    } else {
        // pathological tie fallback: iterative argmax (destructive on g_norms)
        for (int it = 0; it < KPROM; it++) {
            float bv = -3e38f; int bi = 0x7FFFFFFF;
            for (int i = t; i < CANDN; i += 1024) {
                float v = g_norms[i];
                if (v > bv || (v == bv && i < bi)) { bv = v; bi = i; }
            }
            bargmax(bv, bi, wv, wi);
            if (t == 0) { g_top[it] = bi; g_norms[bi] = -3e38f; }
            __syncthreads();
        }
    }
}

__global__ void k_scatter(const float* __restrict__ tok, const int* __restrict__ sptr,
                          float* __restrict__ out_s) {
    int j = blockIdx.x;
    int p = ((sptr[0] + j) % SSZ + SSZ) % SSZ;
    int src = g_top[j];
    ((float4*)(out_s + (size_t)p * DIM))[threadIdx.x] =
        ((const float4*)(tok + (size_t)src * DIM))[threadIdx.x];
}

__global__ void k_q(const float* __restrict__ wq, const float* __restrict__ bq) {
    int j = (blockIdx.x * blockDim.x + threadIdx.x) >> 5;
    int lane = threadIdx.x & 31;
    const float4* wr = (const float4*)(wq + (size_t)j * DIM);
    const float4* mr = (const float4*)g_mean;
    float s = 0.f;
#pragma unroll
    for (int k = 0; k < 8; k++) s += dot4(wr[lane + 32 * k], mr[lane + 32 * k]);
    s = wsum(s);
    if (!lane) g_q[j] = s + bq[j];
}

__global__ void k_v1(const float* __restrict__ wk) {
    int c  = blockIdx.x * 256 + threadIdx.x;
    int r0 = blockIdx.y * (DIM / NVCHUNK);
    float s = 0.f;
    for (int r = r0; r < r0 + (DIM / NVCHUNK); r++)
        s += g_q[r] * wk[(size_t)r * DIM + c];
    g_vpart[blockIdx.y * DIM + c] = s;
}
__global__ void k_v2() {
    int c = threadIdx.x;
    float s = 0.f;
    for (int k = 0; k < NVCHUNK; k++) s += g_vpart[k * DIM + c];
    g_v[c] = s;
}

__global__ void k_scores(const float* __restrict__ out_s) {
    int i = (blockIdx.x * blockDim.x + threadIdx.x) >> 5;
    int lane = threadIdx.x & 31;
    const float4* sr = (const float4*)(out_s + (size_t)i * DIM);
    const float4* vr = (const float4*)g_v;
    float s = 0.f;
#pragma unroll
    for (int k = 0; k < 8; k++) s += dot4(sr[lane + 32 * k], vr[lane + 32 * k]);
    s = wsum(s);
    if (!lane) g_scores[i] = s;
}

__global__ void k_pickcand(const float* __restrict__ out_s) {
    __shared__ float sv[32]; __shared__ int si[32]; __shared__ float sb[32];
    int t = threadIdx.x;
    float v = (t < SSZ) ? g_scores[t] : -3e38f;
    int   i = (t < SSZ) ? t : 0x7FFFFFFF;
    bargmax(v, i, sv, si);
    int best = i;
    float c = out_s[(size_t)best * DIM + t];
    g_cand[t] = c;
    float n2 = bsum(c * c, sb);
    if (t == 0) g_candn2 = n2;
}

// fused: m row norms, sims vs candidate, prefix matrix P + residual norms
__global__ void k_mrow(const float* __restrict__ m) {
    __shared__ float4 scand[256];
    int t = threadIdx.x;
    scand[t] = ((const float4*)g_cand)[t];
    __syncthreads();
    int w = (blockIdx.x * 256 + t) >> 5;
    int lane = t & 31;
    const float4* mr = (const float4*)(m + (size_t)w * DIM);
    float n2 = 0.f, dc = 0.f;
    float4 v0 = make_float4(0, 0, 0, 0);
#pragma unroll
    for (int k = 0; k < 8; k++) {
        float4 v = mr[lane + 32 * k];
        n2 += dot4(v, v);
        dc += dot4(v, scand[lane + 32 * k]);
        if (k == 0) v0 = v;
    }
    n2 = wsum(n2); dc = wsum(dc);
    float sp2 = (lane < 16) ? dot4(v0, v0) : 0.f;
    sp2 = wsum(sp2);
    float rinv = rsqrtf(n2);
    if (lane < 16) {
        float4 pv;
        pv.x = v0.x * rinv; pv.y = v0.y * rinv; pv.z = v0.z * rinv; pv.w = v0.w * rinv;
        ((float4*)(g_P + (size_t)w * PD))[lane] = pv;
    }
    if (!lane) {
        g_mn2[w]  = n2;
        g_sims[w] = dc * rinv * rsqrtf(g_candn2);
        g_res[w]  = sqrtf(fmaxf(0.f, 1.f - sp2 * rinv * rinv));
    }
}

// Cauchy-Schwarz screen: 128x128 tiles, 8x8 per thread, K=64
__global__ void k_screen() {
    int bi = blockIdx.y, bj = blockIdx.x;
    if (bi < bj) return;
    extern __shared__ float sm[];
    float* sPi = sm;
    float* sPj = sm + TB * LDP;
    __shared__ float sri[TB], srj[TB];
    int t = threadIdx.x;
    int i0 = bi * TB, j0 = bj * TB;
#pragma unroll
    for (int k = 0; k < 8; k++) {
        int id = t + 256 * k, row = id >> 4, col = (id & 15) * 4;
        *(float4*)&sPi[row * LDP + col] = *(const float4*)&g_P[(size_t)(i0 + row) * PD + col];
        *(float4*)&sPj[row * LDP + col] = *(const float4*)&g_P[(size_t)(j0 + row) * PD + col];
    }
    if (t < TB) { sri[t] = g_res[i0 + t]; srj[t] = g_res[j0 + t]; }
    __syncthreads();
    int tx = t & 15, ty = t >> 4;
    float acc[8][8];
#pragma unroll
    for (int a = 0; a < 8; a++)
#pragma unroll
        for (int b = 0; b < 8; b++) acc[a][b] = 0.f;
    for (int d = 0; d < PD; d += 4) {
        float4 A[8], B[8];
#pragma unroll
        for (int a = 0; a < 8; a++) A[a] = *(float4*)&sPi[(ty + 16 * a) * LDP + d];
#pragma unroll
        for (int b = 0; b < 8; b++) B[b] = *(float4*)&sPj[(tx + 16 * b) * LDP + d];
#pragma unroll
        for (int a = 0; a < 8; a++)
#pragma unroll
            for (int b = 0; b < 8; b++) acc[a][b] += dot4(A[a], B[b]);
    }
#pragma unroll
    for (int a = 0; a < 8; a++) {
        int i = i0 + ty + 16 * a;
#pragma unroll
        for (int b = 0; b < 8; b++) {
            int j = j0 + tx + 16 * b;
            if (i > j) {
                float bound = acc[a][b] + sri[ty + 16 * a] * srj[tx + 16 * b];
                if (bound > SCREEN_T) {
                    int p = atomicAdd(&g_npairs, 1);
                    if (p < PAIR_CAP) { g_pairs[2 * p] = i; g_pairs[2 * p + 1] = j; }
                }
            }
        }
    }
}

__global__ void k_exact(const float* __restrict__ m) {
    int np = g_npairs; if (np > PAIR_CAP) np = PAIR_CAP;
    int p = blockIdx.x;
    if (p >= np) return;
    int i = g_pairs[2 * p], j = g_pairs[2 * p + 1];
    int t = threadIdx.x;
    float s = dot4(((const float4*)(m + (size_t)i * DIM))[t],
                   ((const float4*)(m + (size_t)j * DIM))[t]);
    __shared__ float sb[8];
    int lane = t & 31, wid = t >> 5;
    s = wsum(s);
    if (!lane) sb[wid] = s;
    __syncthreads();
    if (t == 0) {
        float tot = 0.f;
        for (int k = 0; k < 8; k++) tot += sb[k];
        float cosv = tot * rsqrtf(g_mn2[i] * g_mn2[j]);
        unsigned long long key =
            ((unsigned long long)ordf(cosv) << 32) | (0xFFFFFFFFu - (unsigned)(i * MSZ + j));
        atomicMax(&g_intmax, key);
    }
}

// guarded brute-force fallback (runs only if pair list overflowed)
__global__ void k_brute(const float* __restrict__ m) {
    if (g_npairs <= PAIR_CAP) return;
    int i = blockIdx.x;
    if (i == 0) return;
    __shared__ float row[DIM];
    __shared__ unsigned long long bk_;
    for (int e = threadIdx.x; e < DIM; e += 256) row[e] = m[(size_t)i * DIM + e];
    if (threadIdx.x == 0) bk_ = 0ull;
    __syncthreads();
    float bc = -2.f; int bf = 0;
    for (int j = threadIdx.x; j < i; j += 256) {
        float s = 0.f;
        const float* mj = m + (size_t)j * DIM;
        for (int e = 0; e < DIM; e++) s += row[e] * mj[e];
        float c = s * rsqrtf(g_mn2[i] * g_mn2[j]);
        if (c > bc) { bc = c; bf = i * MSZ + j; }
    }
    unsigned long long key = ((unsigned long long)ordf(bc) << 32) | (0xFFFFFFFFu - (unsigned)bf);
    atomicMax(&bk_, key);
    __syncthreads();
    if (threadIdx.x == 0) atomicMax(&g_intmax, bk_);
}

// M-tier branch resolution and writes
__global__ void k_decide(const float* __restrict__ m, const float* __restrict__ mu,
                         float* __restrict__ out_m, float* __restrict__ out_mu) {
    __shared__ float sv[32]; __shared__ int si[32]; __shared__ float sb[32];
    __shared__ int s_any;
    int t = threadIdx.x;
    if (t == 0) s_any = 0;
    __syncthreads();
    float musum = 0.f, mn = 3e38f; int mni = 0x7FFFFFFF; int anyz = 0;
    for (int i = t; i < MSZ; i += 1024) {
        float u = mu[i];
        musum += u;
        if (u < mn) { mn = u; mni = i; }
        anyz |= (u == 0.f);
    }
    if (anyz) atomicOr(&s_any, 1);
    float mu_mean = bsum(musum, sb) / (float)MSZ;
    bargmin(mn, mni, sv, si);
    int li = mni;
    __syncthreads();
    int any0 = s_any;
    // sims argmax
    float smax = -3e38f; int smi = 0x7FFFFFFF;
    for (int i = t; i < MSZ; i += 1024) {
        float s = g_sims[i];
        if (s > smax || (s == smax && i < smi)) { smax = s; smi = i; }
    }
    bargmax(smax, smi, sv, si);
    int msi = smi; float simcand = smax;
    // decode internal max
    float cosint = -2.f; int i1 = 0, i2 = 0;
    if (g_npairs > 0) {
        unsigned long long kk = g_intmax;
        cosint = deordf((unsigned)(kk >> 32));
        unsigned fl = 0xFFFFFFFFu - (unsigned)(kk & 0xFFFFFFFFu);
        i1 = fl / MSZ; i2 = fl % MSZ;
    }
    if (any0) {
        out_m[(size_t)li * DIM + t] = g_cand[t];
        if (t == 0) out_mu[li] = mu_mean + 1e-5f;
    } else if (simcand > MERGE_T) {
        float merged = (m[(size_t)msi * DIM + t] + g_cand[t]) * 0.5f;
        float n2 = bsum(merged * merged, sb);
        float dn = fmaxf(sqrtf(n2), 1e-12f);
        out_m[(size_t)msi * DIM + t] = merged / dn;
        if (t == 0) out_mu[msi] = (mu[msi] + mu_mean) * 0.5f;
    } else if (cosint > MERGE_T) {
        float merged = (m[(size_t)i1 * DIM + t] + m[(size_t)i2 * DIM + t]) * 0.5f;
        float n2 = bsum(merged * merged, sb);
        float dn = fmaxf(sqrtf(n2), 1e-12f);
        out_m[(size_t)i1 * DIM + t] = merged / dn;
        out_m[(size_t)i2 * DIM + t] = g_cand[t];
        if (t == 0) {
            float nu1 = (mu[i1] + mu[i2]) * 0.5f;
            out_mu[i1] = nu1;
            float mean2 = mu_mean + (nu1 - mu[i1]) / (float)MSZ;
            out_mu[i2] = mean2 + 1e-5f;
        }
    } else {
        if (g_candn2 > g_mn2[li]) {
            out_m[(size_t)li * DIM + t] = g_cand[t];
            if (t == 0) out_mu[li] = mu_mean + 1e-5f;
        }
    }
}

// L-tier consolidation + s_ptr output
__global__ void k_ltier(const float* __restrict__ l_in, const float* __restrict__ lu,
                        const int* __restrict__ sptr,
                        const float* __restrict__ out_m, const float* __restrict__ out_mu,
                        float* __restrict__ out_l, float* __restrict__ out_lu,
                        float* __restrict__ out_ptr) {
    __shared__ float sv[32]; __shared__ int si[32]; __shared__ float sb[32];
    int t = threadIdx.x;
    float mx = -3e38f; int mxi = 0x7FFFFFFF;
    for (int i = t; i < MSZ; i += 1024) {
        float u = out_mu[i];
        if (u > mx || (u == mx && i < mxi)) { mx = u; mxi = i; }
    }
    bargmax(mx, mxi, sv, si);
    int mi = mxi;
    float lsum = 0.f, lmn = 3e38f; int lmni = 0x7FFFFFFF;
    for (int i = t; i < LSZ; i += 1024) {
        float u = lu[i];
        lsum += u;
        if (u < lmn) { lmn = u; lmni = i; }
    }
    float ltot = bsum(lsum, sb);
    bargmin(lmn, lmni, sv, si);
    int lj = lmni;
    out_l[(size_t)lj * DIM + t] =
        0.9f * l_in[(size_t)lj * DIM + t] + 0.1f * out_m[(size_t)mi * DIM + t];
    if (t == 0) {
        out_lu[lj] = ltot / (float)LSZ;
        out_ptr[0] = (float)(((sptr[0] + KPROM) % SSZ + SSZ) % SSZ);
    }
}

// ------------- host -------------
extern "C" void kernel_launch(void* const* d_in, const int* in_sizes, int n_in,
                              void* d_out, int out_size) {
    const float* tok  = (const float*)d_in[0];
    const float* s_in = (const float*)d_in[1];
    const float* m_in = (const float*)d_in[2];
    const float* l_in = (const float*)d_in[3];
    const float* mu   = (const float*)d_in[4];
    const float* lu   = (const float*)d_in[5];
    const float* wq   = (const float*)d_in[6];
    const float* bq   = (const float*)d_in[7];
    const float* wk   = (const float*)d_in[8];
    // d_in[9] = bk: provably unused (constant shift under argmax)
    const int*   sptr = (const int*)d_in[10];

    float* out    = (float*)d_out;
    float* out_s  = out;
    float* out_m  = out_s + (size_t)SSZ * DIM;
    float* out_l  = out_m + (size_t)MSZ * DIM;
    float* out_mu = out_l + (size_t)LSZ * DIM;
    float* out_lu = out_mu + MSZ;
    float* out_ptr = out_lu + LSZ;

    cudaFuncSetAttribute(k_screen, cudaFuncAttributeMaxDynamicSharedMemorySize,
                         2 * TB * LDP * sizeof(float));

    k_init<<<1, 1>>>();
    k_copy4<<<(SSZ * DIM / 4 + 255) / 256, 256>>>((const float4*)s_in, (float4*)out_s, SSZ * DIM / 4);
    k_copy4<<<(MSZ * DIM / 4 + 255) / 256, 256>>>((const float4*)m_in, (float4*)out_m, MSZ * DIM / 4);
    k_copy4<<<(MSZ / 4 + 255) / 256, 256>>>((const float4*)mu, (float4*)out_mu, MSZ / 4);
    k_copy4<<<(LSZ / 4 + 255) / 256, 256>>>((const float4*)lu, (float4*)out_lu, LSZ / 4);
    k_lmean1<<<dim3(DIM / 256, NLCHUNK), 256>>>(l_in, out_l);
    k_lmean2<<<1, 1024>>>();
    k_toknorm<<<CANDN / 32, 1024>>>(tok);
    k_topk<<<1, 1024>>>();
    k_scatter<<<KPROM, 256>>>(tok, sptr, out_s);
    k_q<<<32, 1024>>>(wq, bq);
    k_v1<<<dim3(DIM / 256, NVCHUNK), 256>>>(wk);
    k_v2<<<1, 1024>>>();
    k_scores<<<SSZ / 32, 1024>>>(out_s);
    k_pickcand<<<1, 1024>>>(out_s);
    k_mrow<<<MSZ / 8, 256>>>(m_in);
    k_screen<<<dim3(MSZ / TB, MSZ / TB), 256, 2 * TB * LDP * sizeof(float)>>>();
    k_exact<<<1024, 256>>>(m_in);
    k_brute<<<MSZ, 256>>>(m_in);
    k_decide<<<1, 1024>>>(m_in, mu, out_m, out_mu);
    k_ltier<<<1, 1024>>>(l_in, lu, sptr, out_m, out_mu, out_l, out_lu, out_ptr);
}

// round 3
// speedup vs baseline: 1.1746x; 1.1746x over previous
#include <cuda_runtime.h>

#define DIM   1024
#define CANDN 16384
#define SSZ   512
#define MSZ   4096
#define LSZ   8192
#define KPROM 128
#define PD    64
#define PAIR_CAP 65536
#define NLCHUNK 32
#define NVCHUNK 16
#define TB   128
#define NBT  32              // MSZ/TB
#define NTRI (NBT*(NBT+1)/2) // 528
#define LDP  68
#define SCREEN_T 0.979f
#define MERGE_T  0.98f

// ------------- scratch (device globals; no allocation) -------------
__device__ float g_norms[CANDN];
__device__ int   g_top[KPROM];
__device__ float g_lpart[NLCHUNK * DIM];
__device__ float g_mean[DIM];
__device__ float g_q[DIM];
__device__ float g_vpart[NVCHUNK * DIM];
__device__ float g_v[DIM];
__device__ float g_scores[SSZ];
__device__ float g_cand[DIM];
__device__ float g_candn2;
__device__ float g_mn2[MSZ];
__device__ float g_sims[MSZ];
__device__ float g_P[MSZ * PD];
__device__ float g_res[MSZ];
__device__ int   g_pairs[PAIR_CAP * 2];
__device__ int   g_npairs;
__device__ unsigned long long g_intmax;

// ------------- helpers -------------
__device__ __forceinline__ float dot4(float4 a, float4 b) {
    return a.x*b.x + a.y*b.y + a.z*b.z + a.w*b.w;
}
__device__ __forceinline__ float wsum(float v) {
#pragma unroll
    for (int o = 16; o; o >>= 1) v += __shfl_xor_sync(0xFFFFFFFFu, v, o);
    return v;
}
__device__ __forceinline__ unsigned ordf(float f) {
    unsigned u = __float_as_uint(f);
    return (u & 0x80000000u) ? ~u : (u | 0x80000000u);
}
__device__ __forceinline__ float deordf(unsigned u) {
    return (u & 0x80000000u) ? __uint_as_float(u & 0x7FFFFFFFu) : __uint_as_float(~u);
}
__device__ __forceinline__ float bsum(float v, float* sbuf) {
    int t = threadIdx.x, lane = t & 31, wid = t >> 5;
    v = wsum(v);
    if (!lane) sbuf[wid] = v;
    __syncthreads();
    int nw = blockDim.x >> 5;
    if (wid == 0) {
        float x = (lane < nw) ? sbuf[lane] : 0.f;
        x = wsum(x);
        if (!lane) sbuf[0] = x;
    }
    __syncthreads();
    v = sbuf[0];
    __syncthreads();
    return v;
}
__device__ __forceinline__ void bargmax(float& bv, int& bi, float* sv, int* si) {
    int t = threadIdx.x, lane = t & 31, wid = t >> 5;
#pragma unroll
    for (int o = 16; o; o >>= 1) {
        float ov = __shfl_xor_sync(0xFFFFFFFFu, bv, o);
        int   oi = __shfl_xor_sync(0xFFFFFFFFu, bi, o);
        if (ov > bv || (ov == bv && oi < bi)) { bv = ov; bi = oi; }
    }
    if (!lane) { sv[wid] = bv; si[wid] = bi; }
    __syncthreads();
    int nw = blockDim.x >> 5;
    if (wid == 0) {
        float xv = (lane < nw) ? sv[lane] : -3e38f;
        int   xi = (lane < nw) ? si[lane] : 0x7FFFFFFF;
#pragma unroll
        for (int o = 16; o; o >>= 1) {
            float ov = __shfl_xor_sync(0xFFFFFFFFu, xv, o);
            int   oi = __shfl_xor_sync(0xFFFFFFFFu, xi, o);
            if (ov > xv || (ov == xv && oi < xi)) { xv = ov; xi = oi; }
        }
        if (!lane) { sv[0] = xv; si[0] = xi; }
    }
    __syncthreads();
    bv = sv[0]; bi = si[0];
    __syncthreads();
}
__device__ __forceinline__ void bargmin(float& bv, int& bi, float* sv, int* si) {
    int t = threadIdx.x, lane = t & 31, wid = t >> 5;
#pragma unroll
    for (int o = 16; o; o >>= 1) {
        float ov = __shfl_xor_sync(0xFFFFFFFFu, bv, o);
        int   oi = __shfl_xor_sync(0xFFFFFFFFu, bi, o);
        if (ov < bv || (ov == bv && oi < bi)) { bv = ov; bi = oi; }
    }
    if (!lane) { sv[wid] = bv; si[wid] = bi; }
    __syncthreads();
    int nw = blockDim.x >> 5;
    if (wid == 0) {
        float xv = (lane < nw) ? sv[lane] : 3e38f;
        int   xi = (lane < nw) ? si[lane] : 0x7FFFFFFF;
#pragma unroll
        for (int o = 16; o; o >>= 1) {
            float ov = __shfl_xor_sync(0xFFFFFFFFu, xv, o);
            int   oi = __shfl_xor_sync(0xFFFFFFFFu, xi, o);
            if (ov < xv || (ov == xv && oi < xi)) { xv = ov; xi = oi; }
        }
        if (!lane) { sv[0] = xv; si[0] = xi; }
    }
    __syncthreads();
    bv = sv[0]; bi = si[0];
    __syncthreads();
}

// ------------- kernels -------------
__global__ void k_init() { g_npairs = 0; g_intmax = 0ull; }

// copy out_m (grid-stride float4)
__global__ void k_copy_m(const float4* __restrict__ s, float4* __restrict__ d) {
    int n = MSZ * DIM / 4;
    for (int i = blockIdx.x * blockDim.x + threadIdx.x; i < n; i += gridDim.x * blockDim.x)
        d[i] = s[i];
}
// fused small copies: out_s, out_mu, out_lu
__global__ void k_copy_small(const float4* __restrict__ s_in, float4* __restrict__ out_s,
                             const float4* __restrict__ mu, float4* __restrict__ out_mu,
                             const float4* __restrict__ lu, float4* __restrict__ out_lu) {
    const int nS = SSZ * DIM / 4, nMu = MSZ / 4, nLu = LSZ / 4;
    int i = blockIdx.x * blockDim.x + threadIdx.x;
    int stride = gridDim.x * blockDim.x;
    for (int k = i; k < nS; k += stride) out_s[k] = s_in[k];
    for (int k = i; k < nMu; k += stride) out_mu[k] = mu[k];
    for (int k = i; k < nLu; k += stride) out_lu[k] = lu[k];
}

__global__ void k_lmean1(const float* __restrict__ l, float* __restrict__ outl) {
    int c  = blockIdx.x * 256 + threadIdx.x;
    int r0 = blockIdx.y * (LSZ / NLCHUNK);
    float s = 0.f;
    for (int r = r0; r < r0 + (LSZ / NLCHUNK); r++) {
        float v = l[(size_t)r * DIM + c];
        outl[(size_t)r * DIM + c] = v;
        s += v;
    }
    g_lpart[blockIdx.y * DIM + c] = s;
}
__global__ void k_lmean2() {
    int c = threadIdx.x;
    float s = 0.f;
    for (int k = 0; k < NLCHUNK; k++) s += g_lpart[k * DIM + c];
    g_mean[c] = s / (float)LSZ;
}

__global__ void k_toknorm(const float* __restrict__ tok) {
    int w = (blockIdx.x * blockDim.x + threadIdx.x) >> 5;
    int lane = threadIdx.x & 31;
    const float4* p = (const float4*)(tok + (size_t)w * DIM);
    float s = 0.f;
#pragma unroll
    for (int k = 0; k < 8; k++) { float4 v = p[lane + 32 * k]; s += dot4(v, v); }
    s = wsum(s);
    if (!lane) g_norms[w] = s;
}

__global__ void k_topk() {
    __shared__ int   hist[256];
    __shared__ float sval[1024];
    __shared__ int   sidx[1024];
    __shared__ int   s_cnt, s_b1;
    __shared__ float wv[32]; __shared__ int wi[32];
    int t = threadIdx.x;
    if (t < 256) hist[t] = 0;
    __syncthreads();
    for (int i = t; i < CANDN; i += 1024)
        atomicAdd(&hist[ordf(g_norms[i]) >> 24], 1);
    __syncthreads();
    if (t == 0) {
        int c = 0, b = 255;
        for (; b > 0; b--) { if (c + hist[b] >= KPROM) break; c += hist[b]; }
        s_b1 = b; s_cnt = 0;
    }
    __syncthreads();
    int b1 = s_b1;
    for (int i = t; i < CANDN; i += 1024) {
        float v = g_norms[i];
        if ((int)(ordf(v) >> 24) >= b1) {
            int p = atomicAdd(&s_cnt, 1);
            if (p < 1024) { sval[p] = v; sidx[p] = i; }
        }
    }
    __syncthreads();
    int M = s_cnt;
    if (M <= 1024) {
        if (t < M) {
            float v = sval[t]; int id = sidx[t]; int r = 0;
            for (int f = 0; f < M; f++) {
                float vf = sval[f]; int idf = sidx[f];
                r += (vf > v) || (vf == v && idf < id);
            }
            if (r < KPROM) g_top[r] = id;
        }
    } else {
        for (int it = 0; it < KPROM; it++) {
            float bv = -3e38f; int bi = 0x7FFFFFFF;
            for (int i = t; i < CANDN; i += 1024) {
                float v = g_norms[i];
                if (v > bv || (v == bv && i < bi)) { bv = v; bi = i; }
            }
            bargmax(bv, bi, wv, wi);
            if (t == 0) { g_top[it] = bi; g_norms[bi] = -3e38f; }
            __syncthreads();
        }
    }
}

__global__ void k_scatter(const float* __restrict__ tok, const int* __restrict__ sptr,
                          float* __restrict__ out_s) {
    int j = blockIdx.x;
    int p = ((sptr[0] + j) % SSZ + SSZ) % SSZ;
    int src = g_top[j];
    ((float4*)(out_s + (size_t)p * DIM))[threadIdx.x] =
        ((const float4*)(tok + (size_t)src * DIM))[threadIdx.x];
}

__global__ void k_q(const float* __restrict__ wq, const float* __restrict__ bq) {
    int j = (blockIdx.x * blockDim.x + threadIdx.x) >> 5;
    int lane = threadIdx.x & 31;
    const float4* wr = (const float4*)(wq + (size_t)j * DIM);
    const float4* mr = (const float4*)g_mean;
    float s = 0.f;
#pragma unroll
    for (int k = 0; k < 8; k++) s += dot4(wr[lane + 32 * k], mr[lane + 32 * k]);
    s = wsum(s);
    if (!lane) g_q[j] = s + bq[j];
}

__global__ void k_v1(const float* __restrict__ wk) {
    int c  = blockIdx.x * 256 + threadIdx.x;
    int r0 = blockIdx.y * (DIM / NVCHUNK);
    float s = 0.f;
    for (int r = r0; r < r0 + (DIM / NVCHUNK); r++)
        s += g_q[r] * wk[(size_t)r * DIM + c];
    g_vpart[blockIdx.y * DIM + c] = s;
}
__global__ void k_v2() {
    int c = threadIdx.x;
    float s = 0.f;
    for (int k = 0; k < NVCHUNK; k++) s += g_vpart[k * DIM + c];
    g_v[c] = s;
}

__global__ void k_scores(const float* __restrict__ out_s) {
    int i = (blockIdx.x * blockDim.x + threadIdx.x) >> 5;
    int lane = threadIdx.x & 31;
    const float4* sr = (const float4*)(out_s + (size_t)i * DIM);
    const float4* vr = (const float4*)g_v;
    float s = 0.f;
#pragma unroll
    for (int k = 0; k < 8; k++) s += dot4(sr[lane + 32 * k], vr[lane + 32 * k]);
    s = wsum(s);
    if (!lane) g_scores[i] = s;
}

__global__ void k_pickcand(const float* __restrict__ out_s) {
    __shared__ float sv[32]; __shared__ int si[32]; __shared__ float sb[32];
    int t = threadIdx.x;
    float v = (t < SSZ) ? g_scores[t] : -3e38f;
    int   i = (t < SSZ) ? t : 0x7FFFFFFF;
    bargmax(v, i, sv, si);
    int best = i;
    float c = out_s[(size_t)best * DIM + t];
    g_cand[t] = c;
    float n2 = bsum(c * c, sb);
    if (t == 0) g_candn2 = n2;
}

// candidate-INDEPENDENT prep: m row norms, prefix matrix P, residual norms
__global__ void k_mprep(const float* __restrict__ m) {
    int t = threadIdx.x;
    int w = (blockIdx.x * 256 + t) >> 5;
    int lane = t & 31;
    const float4* mr = (const float4*)(m + (size_t)w * DIM);
    float n2 = 0.f;
    float4 v0 = make_float4(0, 0, 0, 0);
#pragma unroll
    for (int k = 0; k < 8; k++) {
        float4 v = mr[lane + 32 * k];
        n2 += dot4(v, v);
        if (k == 0) v0 = v;
    }
    n2 = wsum(n2);
    float sp2 = (lane < 16) ? dot4(v0, v0) : 0.f;
    sp2 = wsum(sp2);
    float rinv = rsqrtf(n2);
    if (lane < 16) {
        float4 pv;
        pv.x = v0.x * rinv; pv.y = v0.y * rinv; pv.z = v0.z * rinv; pv.w = v0.w * rinv;
        ((float4*)(g_P + (size_t)w * PD))[lane] = pv;
    }
    if (!lane) {
        g_mn2[w] = n2;
        g_res[w] = sqrtf(fmaxf(0.f, 1.f - sp2 * rinv * rinv));
    }
}

// candidate-dependent sims (depends on pickcand + mprep)
__global__ void k_msims(const float* __restrict__ m) {
    __shared__ float4 scand[256];
    int t = threadIdx.x;
    scand[t] = ((const float4*)g_cand)[t];
    __syncthreads();
    int lane = t & 31;
    float rc = rsqrtf(g_candn2);
    for (int w = (blockIdx.x * 256 + t) >> 5; w < MSZ; w += (gridDim.x * 256) >> 5) {
        const float4* mr = (const float4*)(m + (size_t)w * DIM);
        float dc = 0.f;
#pragma unroll
        for (int k = 0; k < 8; k++) dc += dot4(mr[lane + 32 * k], scand[lane + 32 * k]);
        dc = wsum(dc);
        if (!lane) g_sims[w] = dc * rsqrtf(g_mn2[w]) * rc;
    }
}

// Cauchy-Schwarz screen: lower-triangular 1D grid, 128x128 tiles, 8x8/thread, K=64
__global__ void k_screen() {
    int k = blockIdx.x;
    int bi = (int)((sqrtf(8.f * (float)k + 1.f) - 1.f) * 0.5f);
    while ((bi + 1) * (bi + 2) / 2 <= k) bi++;
    while (bi * (bi + 1) / 2 > k) bi--;
    int bj = k - bi * (bi + 1) / 2;
    extern __shared__ float sm[];
    float* sPi = sm;
    float* sPj = sm + TB * LDP;
    __shared__ float sri[TB], srj[TB];
    int t = threadIdx.x;
    int i0 = bi * TB, j0 = bj * TB;
#pragma unroll
    for (int q = 0; q < 8; q++) {
        int id = t + 256 * q, row = id >> 4, col = (id & 15) * 4;
        *(float4*)&sPi[row * LDP + col] = *(const float4*)&g_P[(size_t)(i0 + row) * PD + col];
        *(float4*)&sPj[row * LDP + col] = *(const float4*)&g_P[(size_t)(j0 + row) * PD + col];
    }
    if (t < TB) { sri[t] = g_res[i0 + t]; srj[t] = g_res[j0 + t]; }
    __syncthreads();
    int tx = t & 15, ty = t >> 4;
    float acc[8][8];
#pragma unroll
    for (int a = 0; a < 8; a++)
#pragma unroll
        for (int b = 0; b < 8; b++) acc[a][b] = 0.f;
    for (int d = 0; d < PD; d += 4) {
        float4 A[8], B[8];
#pragma unroll
        for (int a = 0; a < 8; a++) A[a] = *(float4*)&sPi[(ty + 16 * a) * LDP + d];
#pragma unroll
        for (int b = 0; b < 8; b++) B[b] = *(float4*)&sPj[(tx + 16 * b) * LDP + d];
#pragma unroll
        for (int a = 0; a < 8; a++)
#pragma unroll
            for (int b = 0; b < 8; b++) acc[a][b] += dot4(A[a], B[b]);
    }
#pragma unroll
    for (int a = 0; a < 8; a++) {
        int i = i0 + ty + 16 * a;
#pragma unroll
        for (int b = 0; b < 8; b++) {
            int j = j0 + tx + 16 * b;
            if (i > j) {
                float bound = acc[a][b] + sri[ty + 16 * a] * srj[tx + 16 * b];
                if (bound > SCREEN_T) {
                    int p = atomicAdd(&g_npairs, 1);
                    if (p < PAIR_CAP) { g_pairs[2 * p] = i; g_pairs[2 * p + 1] = j; }
                }
            }
        }
    }
}

// exact cosines for surviving pairs (persistent, small grid) + guarded brute fallback
__global__ void k_exactbrute(const float* __restrict__ m) {
    __shared__ float sb[8];
    __shared__ unsigned long long bk_;
    int t = threadIdx.x, lane = t & 31, wid = t >> 5;
    int np = g_npairs;
    if (np <= PAIR_CAP) {
        for (int p = blockIdx.x; p < np; p += gridDim.x) {
            int i = g_pairs[2 * p], j = g_pairs[2 * p + 1];
            float s = dot4(((const float4*)(m + (size_t)i * DIM))[t],
                           ((const float4*)(m + (size_t)j * DIM))[t]);
            s = wsum(s);
            if (!lane) sb[wid] = s;
            __syncthreads();
            if (t == 0) {
                float tot = 0.f;
                for (int q = 0; q < 8; q++) tot += sb[q];
                float cosv = tot * rsqrtf(g_mn2[i] * g_mn2[j]);
                unsigned long long key =
                    ((unsigned long long)ordf(cosv) << 32) | (0xFFFFFFFFu - (unsigned)(i * MSZ + j));
                atomicMax(&g_intmax, key);
            }
            __syncthreads();
        }
    } else {
        // pathological fallback: full brute force
        if (t == 0) bk_ = 0ull;
        __syncthreads();
        for (int i = blockIdx.x; i < MSZ; i += gridDim.x) {
            if (i == 0) continue;
            float bc = -2.f; int bf = 0;
            for (int j = t; j < i; j += 256) {
                float s = 0.f;
                const float* mi = m + (size_t)i * DIM;
                const float* mj = m + (size_t)j * DIM;
                for (int e = 0; e < DIM; e++) s += mi[e] * mj[e];
                float c = s * rsqrtf(g_mn2[i] * g_mn2[j]);
                if (c > bc) { bc = c; bf = i * MSZ + j; }
            }
            unsigned long long key = ((unsigned long long)ordf(bc) << 32) | (0xFFFFFFFFu - (unsigned)bf);
            atomicMax(&bk_, key);
        }
        __syncthreads();
        if (t == 0) atomicMax(&g_intmax, bk_);
    }
}

__global__ void k_decide(const float* __restrict__ m, const float* __restrict__ mu,
                         float* __restrict__ out_m, float* __restrict__ out_mu) {
    __shared__ float sv[32]; __shared__ int si[32]; __shared__ float sb[32];
    __shared__ int s_any;
    int t = threadIdx.x;
    if (t == 0) s_any = 0;
    __syncthreads();
    float musum = 0.f, mn = 3e38f; int mni = 0x7FFFFFFF; int anyz = 0;
    for (int i = t; i < MSZ; i += 1024) {
        float u = mu[i];
        musum += u;
        if (u < mn) { mn = u; mni = i; }
        anyz |= (u == 0.f);
    }
    if (anyz) atomicOr(&s_any, 1);
    float mu_mean = bsum(musum, sb) / (float)MSZ;
    bargmin(mn, mni, sv, si);
    int li = mni;
    __syncthreads();
    int any0 = s_any;
    float smax = -3e38f; int smi = 0x7FFFFFFF;
    for (int i = t; i < MSZ; i += 1024) {
        float s = g_sims[i];
        if (s > smax || (s == smax && i < smi)) { smax = s; smi = i; }
    }
    bargmax(smax, smi, sv, si);
    int msi = smi; float simcand = smax;
    float cosint = -2.f; int i1 = 0, i2 = 0;
    if (g_npairs > 0) {
        unsigned long long kk = g_intmax;
        cosint = deordf((unsigned)(kk >> 32));
        unsigned fl = 0xFFFFFFFFu - (unsigned)(kk & 0xFFFFFFFFu);
        i1 = fl / MSZ; i2 = fl % MSZ;
    }
    if (any0) {
        out_m[(size_t)li * DIM + t] = g_cand[t];
        if (t == 0) out_mu[li] = mu_mean + 1e-5f;
    } else if (simcand > MERGE_T) {
        float merged = (m[(size_t)msi * DIM + t] + g_cand[t]) * 0.5f;
        float n2 = bsum(merged * merged, sb);
        float dn = fmaxf(sqrtf(n2), 1e-12f);
        out_m[(size_t)msi * DIM + t] = merged / dn;
        if (t == 0) out_mu[msi] = (mu[msi] + mu_mean) * 0.5f;
    } else if (cosint > MERGE_T) {
        float merged = (m[(size_t)i1 * DIM + t] + m[(size_t)i2 * DIM + t]) * 0.5f;
        float n2 = bsum(merged * merged, sb);
        float dn = fmaxf(sqrtf(n2), 1e-12f);
        out_m[(size_t)i1 * DIM + t] = merged / dn;
        out_m[(size_t)i2 * DIM + t] = g_cand[t];
        if (t == 0) {
            float nu1 = (mu[i1] + mu[i2]) * 0.5f;
            out_mu[i1] = nu1;
            float mean2 = mu_mean + (nu1 - mu[i1]) / (float)MSZ;
            out_mu[i2] = mean2 + 1e-5f;
        }
    } else {
        if (g_candn2 > g_mn2[li]) {
            out_m[(size_t)li * DIM + t] = g_cand[t];
            if (t == 0) out_mu[li] = mu_mean + 1e-5f;
        }
    }
}

__global__ void k_ltier(const float* __restrict__ l_in, const float* __restrict__ lu,
                        const int* __restrict__ sptr,
                        const float* __restrict__ out_m, const float* __restrict__ out_mu,
                        float* __restrict__ out_l, float* __restrict__ out_lu,
                        float* __restrict__ out_ptr) {
    __shared__ float sv[32]; __shared__ int si[32]; __shared__ float sb[32];
    int t = threadIdx.x;
    float mx = -3e38f; int mxi = 0x7FFFFFFF;
    for (int i = t; i < MSZ; i += 1024) {
        float u = out_mu[i];
        if (u > mx || (u == mx && i < mxi)) { mx = u; mxi = i; }
    }
    bargmax(mx, mxi, sv, si);
    int mi = mxi;
    float lsum = 0.f, lmn = 3e38f; int lmni = 0x7FFFFFFF;
    for (int i = t; i < LSZ; i += 1024) {
        float u = lu[i];
        lsum += u;
        if (u < lmn) { lmn = u; lmni = i; }
    }
    float ltot = bsum(lsum, sb);
    bargmin(lmn, lmni, sv, si);
    int lj = lmni;
    out_l[(size_t)lj * DIM + t] =
        0.9f * l_in[(size_t)lj * DIM + t] + 0.1f * out_m[(size_t)mi * DIM + t];
    if (t == 0) {
        out_lu[lj] = ltot / (float)LSZ;
        out_ptr[0] = (float)(((sptr[0] + KPROM) % SSZ + SSZ) % SSZ);
    }
}

// ------------- host -------------
extern "C" void kernel_launch(void* const* d_in, const int* in_sizes, int n_in,
                              void* d_out, int out_size) {
    const float* tok  = (const float*)d_in[0];
    const float* s_in = (const float*)d_in[1];
    const float* m_in = (const float*)d_in[2];
    const float* l_in = (const float*)d_in[3];
    const float* mu   = (const float*)d_in[4];
    const float* lu   = (const float*)d_in[5];
    const float* wq   = (const float*)d_in[6];
    const float* bq   = (const float*)d_in[7];
    const float* wk   = (const float*)d_in[8];
    const int*   sptr = (const int*)d_in[10];

    float* out    = (float*)d_out;
    float* out_s  = out;
    float* out_m  = out_s + (size_t)SSZ * DIM;
    float* out_l  = out_m + (size_t)MSZ * DIM;
    float* out_mu = out_l + (size_t)LSZ * DIM;
    float* out_lu = out_mu + MSZ;
    float* out_ptr = out_lu + LSZ;

    // one-time side-stream/event setup (first call = correctness run, not captured)
    static cudaStream_t sA = 0, sB = 0, sC = 0;
    static cudaEvent_t evRoot = 0, evScopy = 0, evA = 0, evB = 0, evPrep = 0, evC = 0;
    if (!sA) {
        cudaStreamCreateWithFlags(&sA, cudaStreamNonBlocking);
        cudaStreamCreateWithFlags(&sB, cudaStreamNonBlocking);
        cudaStreamCreateWithFlags(&sC, cudaStreamNonBlocking);
        cudaEventCreateWithFlags(&evRoot, cudaEventDisableTiming);
        cudaEventCreateWithFlags(&evScopy, cudaEventDisableTiming);
        cudaEventCreateWithFlags(&evA, cudaEventDisableTiming);
        cudaEventCreateWithFlags(&evB, cudaEventDisableTiming);
        cudaEventCreateWithFlags(&evPrep, cudaEventDisableTiming);
        cudaEventCreateWithFlags(&evC, cudaEventDisableTiming);
        cudaFuncSetAttribute(k_screen, cudaFuncAttributeMaxDynamicSharedMemorySize,
                             2 * TB * LDP * sizeof(float));
    }

    // origin stream (0): init, then fork
    k_init<<<1, 1>>>();
    cudaEventRecord(evRoot, 0);

    // branch A: output copies
    cudaStreamWaitEvent(sA, evRoot, 0);
    k_copy_small<<<512, 256, 0, sA>>>((const float4*)s_in, (float4*)out_s,
                                      (const float4*)mu, (float4*)out_mu,
                                      (const float4*)lu, (float4*)out_lu);
    cudaEventRecord(evScopy, sA);
    k_copy_m<<<2048, 256, 0, sA>>>((const float4*)m_in, (float4*)out_m);
    cudaEventRecord(evA, sA);

    // branch B: l copy+mean -> q -> v
    cudaStreamWaitEvent(sB, evRoot, 0);
    k_lmean1<<<dim3(DIM / 256, NLCHUNK), 256, 0, sB>>>(l_in, out_l);
    k_lmean2<<<1, 1024, 0, sB>>>();
    k_q<<<32, 1024, 0, sB>>>(wq, bq);
    k_v1<<<dim3(DIM / 256, NVCHUNK), 256, 0, sB>>>(wk);
    k_v2<<<1, 1024, 0, sB>>>();
    cudaEventRecord(evB, sB);

    // origin: mprep -> screen -> exact (compute-heavy chain, overlaps everything)
    k_mprep<<<MSZ / 8, 256>>>(m_in);
    cudaEventRecord(evPrep, 0);
    k_screen<<<NTRI, 256, 2 * TB * LDP * sizeof(float)>>>();
    k_exactbrute<<<256, 256>>>(m_in);

    // branch C: token chain -> scores -> candidate -> sims
    cudaStreamWaitEvent(sC, evRoot, 0);
    k_toknorm<<<CANDN / 32, 1024, 0, sC>>>(tok);
    k_topk<<<1, 1024, 0, sC>>>();
    cudaStreamWaitEvent(sC, evScopy, 0);
    k_scatter<<<KPROM, 256, 0, sC>>>(tok, sptr, out_s);
    cudaStreamWaitEvent(sC, evB, 0);
    k_scores<<<SSZ / 32, 1024, 0, sC>>>(out_s);
    k_pickcand<<<1, 1024, 0, sC>>>(out_s);
    cudaStreamWaitEvent(sC, evPrep, 0);
    k_msims<<<128, 256, 0, sC>>>(m_in);
    cudaEventRecord(evC, sC);

    // join all branches into origin, then sequential tail
    cudaStreamWaitEvent(0, evA, 0);
    cudaStreamWaitEvent(0, evC, 0);  // evC transitively covers evB
    k_decide<<<1, 1024>>>(m_in, mu, out_m, out_mu);
    k_ltier<<<1, 1024>>>(l_in, lu, sptr, out_m, out_mu, out_l, out_lu, out_ptr);
}

// round 4
// speedup vs baseline: 2.5971x; 2.2109x over previous
#include <cuda_runtime.h>

#define DIM   1024
#define CANDN 16384
#define SSZ   512
#define MSZ   4096
#define LSZ   8192
#define KPROM 128
#define PD    64
#define PAIR_CAP 65536
#define NLCHUNK 64
#define NVCHUNK 16
#define TB   128
#define NBT  32              // MSZ/TB
#define NTRI (NBT*(NBT+1)/2) // 528
#define LDP  68
#define COLLECT_CAP 2048
#define SCREEN_T 0.979f
#define MERGE_T  0.98f

// ------------- scratch (device globals; no allocation) -------------
__device__ float g_norms[CANDN];
__device__ int   g_top[KPROM];
__device__ float g_lpart[NLCHUNK * DIM];
__device__ float g_mean[DIM];
__device__ float g_q[DIM];
__device__ float g_vpart[NVCHUNK * DIM];
__device__ float g_v[DIM];
__device__ float g_scores[SSZ];
__device__ float g_cand[DIM];
__device__ float g_candn2;
__device__ float g_mn2[MSZ];
__device__ float g_sims[MSZ];
__device__ float g_P[MSZ * PD];
__device__ float g_res[MSZ];
__device__ int   g_pairs[PAIR_CAP * 2];
__device__ int   g_npairs;
__device__ unsigned long long g_intmax;

// ------------- helpers -------------
__device__ __forceinline__ float dot4(float4 a, float4 b) {
    return a.x*b.x + a.y*b.y + a.z*b.z + a.w*b.w;
}
__device__ __forceinline__ float wsum(float v) {
#pragma unroll
    for (int o = 16; o; o >>= 1) v += __shfl_xor_sync(0xFFFFFFFFu, v, o);
    return v;
}
__device__ __forceinline__ unsigned ordf(float f) {
    unsigned u = __float_as_uint(f);
    return (u & 0x80000000u) ? ~u : (u | 0x80000000u);
}
__device__ __forceinline__ float deordf(unsigned u) {
    return (u & 0x80000000u) ? __uint_as_float(u & 0x7FFFFFFFu) : __uint_as_float(~u);
}
__device__ __forceinline__ float bsum(float v, float* sbuf) {
    int t = threadIdx.x, lane = t & 31, wid = t >> 5;
    v = wsum(v);
    if (!lane) sbuf[wid] = v;
    __syncthreads();
    int nw = blockDim.x >> 5;
    if (wid == 0) {
        float x = (lane < nw) ? sbuf[lane] : 0.f;
        x = wsum(x);
        if (!lane) sbuf[0] = x;
    }
    __syncthreads();
    v = sbuf[0];
    __syncthreads();
    return v;
}
__device__ __forceinline__ void bargmax(float& bv, int& bi, float* sv, int* si) {
    int t = threadIdx.x, lane = t & 31, wid = t >> 5;
#pragma unroll
    for (int o = 16; o; o >>= 1) {
        float ov = __shfl_xor_sync(0xFFFFFFFFu, bv, o);
        int   oi = __shfl_xor_sync(0xFFFFFFFFu, bi, o);
        if (ov > bv || (ov == bv && oi < bi)) { bv = ov; bi = oi; }
    }
    if (!lane) { sv[wid] = bv; si[wid] = bi; }
    __syncthreads();
    int nw = blockDim.x >> 5;
    if (wid == 0) {
        float xv = (lane < nw) ? sv[lane] : -3e38f;
        int   xi = (lane < nw) ? si[lane] : 0x7FFFFFFF;
#pragma unroll
        for (int o = 16; o; o >>= 1) {
            float ov = __shfl_xor_sync(0xFFFFFFFFu, xv, o);
            int   oi = __shfl_xor_sync(0xFFFFFFFFu, xi, o);
            if (ov > xv || (ov == xv && oi < xi)) { xv = ov; xi = oi; }
        }
        if (!lane) { sv[0] = xv; si[0] = xi; }
    }
    __syncthreads();
    bv = sv[0]; bi = si[0];
    __syncthreads();
}
__device__ __forceinline__ void bargmin(float& bv, int& bi, float* sv, int* si) {
    int t = threadIdx.x, lane = t & 31, wid = t >> 5;
#pragma unroll
    for (int o = 16; o; o >>= 1) {
        float ov = __shfl_xor_sync(0xFFFFFFFFu, bv, o);
        int   oi = __shfl_xor_sync(0xFFFFFFFFu, bi, o);
        if (ov < bv || (ov == bv && oi < bi)) { bv = ov; bi = oi; }
    }
    if (!lane) { sv[wid] = bv; si[wid] = bi; }
    __syncthreads();
    int nw = blockDim.x >> 5;
    if (wid == 0) {
        float xv = (lane < nw) ? sv[lane] : 3e38f;
        int   xi = (lane < nw) ? si[lane] : 0x7FFFFFFF;
#pragma unroll
        for (int o = 16; o; o >>= 1) {
            float ov = __shfl_xor_sync(0xFFFFFFFFu, xv, o);
            int   oi = __shfl_xor_sync(0xFFFFFFFFu, xi, o);
            if (ov < xv || (ov == xv && oi < xi)) { xv = ov; xi = oi; }
        }
        if (!lane) { sv[0] = xv; si[0] = xi; }
    }
    __syncthreads();
    bv = sv[0]; bi = si[0];
    __syncthreads();
}

// ------------- kernels -------------
__global__ void k_init() { g_npairs = 0; g_intmax = 0ull; }

__global__ void k_copy_m(const float4* __restrict__ s, float4* __restrict__ d) {
    int n = MSZ * DIM / 4;
    for (int i = blockIdx.x * blockDim.x + threadIdx.x; i < n; i += gridDim.x * blockDim.x)
        d[i] = s[i];
}
__global__ void k_copy_small(const float4* __restrict__ s_in, float4* __restrict__ out_s,
                             const float4* __restrict__ mu, float4* __restrict__ out_mu,
                             const float4* __restrict__ lu, float4* __restrict__ out_lu) {
    const int nS = SSZ * DIM / 4, nMu = MSZ / 4, nLu = LSZ / 4;
    int i = blockIdx.x * blockDim.x + threadIdx.x;
    int stride = gridDim.x * blockDim.x;
    for (int k = i; k < nS; k += stride) out_s[k] = s_in[k];
    for (int k = i; k < nMu; k += stride) out_mu[k] = mu[k];
    for (int k = i; k < nLu; k += stride) out_lu[k] = lu[k];
}

__global__ void k_lmean1(const float* __restrict__ l, float* __restrict__ outl) {
    int c  = blockIdx.x * 256 + threadIdx.x;
    int r0 = blockIdx.y * (LSZ / NLCHUNK);
    float s = 0.f;
    for (int r = r0; r < r0 + (LSZ / NLCHUNK); r++) {
        float v = l[(size_t)r * DIM + c];
        outl[(size_t)r * DIM + c] = v;
        s += v;
    }
    g_lpart[blockIdx.y * DIM + c] = s;
}
__global__ void k_lmean2() {
    int c = blockIdx.x * 256 + threadIdx.x;
    float s = 0.f;
    for (int k = 0; k < NLCHUNK; k++) s += g_lpart[k * DIM + c];
    g_mean[c] = s / (float)LSZ;
}

__global__ void k_toknorm(const float* __restrict__ tok) {
    int w = (blockIdx.x * blockDim.x + threadIdx.x) >> 5;
    int lane = threadIdx.x & 31;
    const float4* p = (const float4*)(tok + (size_t)w * DIM);
    float s = 0.f;
#pragma unroll
    for (int k = 0; k < 8; k++) { float4 v = p[lane + 32 * k]; s += dot4(v, v); }
    s = wsum(s);
    if (!lane) g_norms[w] = s;
}

// single-block top-128: 3-pass byte radix select (handles exponent-concentrated data)
__global__ void k_topk() {
    __shared__ int   hist[256];
    __shared__ float sval[COLLECT_CAP];
    __shared__ int   sidx[COLLECT_CAP];
    __shared__ int   s_cnt;
    __shared__ unsigned s_pref;   // accumulated high-byte prefix
    __shared__ int   s_kneed;     // remaining rank within current bucket
    __shared__ float wv[32]; __shared__ int wi[32];
    int t = threadIdx.x;

    if (t == 0) { s_pref = 0; s_kneed = KPROM; }
    // three radix passes over bytes 3,2,1 of ordf key
    for (int pass = 0; pass < 3; pass++) {
        int shift = 24 - 8 * pass;
        if (t < 256) hist[t] = 0;
        __syncthreads();
        unsigned pref = s_pref;
        for (int i = t; i < CANDN; i += 1024) {
            unsigned key = ordf(g_norms[i]);
            if ((key >> (shift + 8)) == pref)
                atomicAdd(&hist[(key >> shift) & 255u], 1);
        }
        __syncthreads();
        if (t == 0) {
            int kneed = s_kneed, cum = 0, b = 255;
            for (; b >= 0; b--) {
                cum += hist[b];
                if (cum >= kneed) break;
            }
            if (b < 0) b = 0;                       // defensive
            s_kneed = kneed - (cum - hist[b]);      // rank within chosen bucket
            s_pref = (s_pref << 8) | (unsigned)b;
        }
        __syncthreads();
    }
    // collect all items with top-24-bit key >= P24; count = (K - kneed) + bucket24_size
    unsigned P24 = s_pref;
    if (t == 0) s_cnt = 0;
    __syncthreads();
    for (int i = t; i < CANDN; i += 1024) {
        float v = g_norms[i];
        if ((ordf(v) >> 8) >= P24) {
            int p = atomicAdd(&s_cnt, 1);
            if (p < COLLECT_CAP) { sval[p] = v; sidx[p] = i; }
        }
    }
    __syncthreads();
    int M = s_cnt;
    if (M <= COLLECT_CAP) {
        // rank-sort (val desc, idx asc); M ~ 128 + few
        for (int s = t; s < M; s += 1024) {
            float v = sval[s]; int id = sidx[s]; int r = 0;
            for (int f = 0; f < M; f++) {
                float vf = sval[f]; int idf = sidx[f];
                r += (vf > v) || (vf == v && idf < id);
            }
            if (r < KPROM) g_top[r] = id;
        }
    } else {
        // adversarial-tie fallback: iterative argmax (destructive on g_norms)
        for (int it = 0; it < KPROM; it++) {
            float bv = -3e38f; int bi = 0x7FFFFFFF;
            for (int i = t; i < CANDN; i += 1024) {
                float v = g_norms[i];
                if (v > bv || (v == bv && i < bi)) { bv = v; bi = i; }
            }
            bargmax(bv, bi, wv, wi);
            if (t == 0) { g_top[it] = bi; g_norms[bi] = -3e38f; }
            __syncthreads();
        }
    }
}

__global__ void k_scatter(const float* __restrict__ tok, const int* __restrict__ sptr,
                          float* __restrict__ out_s) {
    int j = blockIdx.x;
    int p = ((sptr[0] + j) % SSZ + SSZ) % SSZ;
    int src = g_top[j];
    ((float4*)(out_s + (size_t)p * DIM))[threadIdx.x] =
        ((const float4*)(tok + (size_t)src * DIM))[threadIdx.x];
}

__global__ void k_q(const float* __restrict__ wq, const float* __restrict__ bq) {
    int j = (blockIdx.x * blockDim.x + threadIdx.x) >> 5;
    int lane = threadIdx.x & 31;
    const float4* wr = (const float4*)(wq + (size_t)j * DIM);
    const float4* mr = (const float4*)g_mean;
    float s = 0.f;
#pragma unroll
    for (int k = 0; k < 8; k++) s += dot4(wr[lane + 32 * k], mr[lane + 32 * k]);
    s = wsum(s);
    if (!lane) g_q[j] = s + bq[j];
}

__global__ void k_v1(const float* __restrict__ wk) {
    int c  = blockIdx.x * 256 + threadIdx.x;
    int r0 = blockIdx.y * (DIM / NVCHUNK);
    float s = 0.f;
    for (int r = r0; r < r0 + (DIM / NVCHUNK); r++)
        s += g_q[r] * wk[(size_t)r * DIM + c];
    g_vpart[blockIdx.y * DIM + c] = s;
}
__global__ void k_v2() {
    int c = threadIdx.x;
    float s = 0.f;
    for (int k = 0; k < NVCHUNK; k++) s += g_vpart[k * DIM + c];
    g_v[c] = s;
}

__global__ void k_scores(const float* __restrict__ out_s) {
    int i = (blockIdx.x * blockDim.x + threadIdx.x) >> 5;
    int lane = threadIdx.x & 31;
    const float4* sr = (const float4*)(out_s + (size_t)i * DIM);
    const float4* vr = (const float4*)g_v;
    float s = 0.f;
#pragma unroll
    for (int k = 0; k < 8; k++) s += dot4(sr[lane + 32 * k], vr[lane + 32 * k]);
    s = wsum(s);
    if (!lane) g_scores[i] = s;
}

__global__ void k_pickcand(const float* __restrict__ out_s) {
    __shared__ float sv[32]; __shared__ int si[32]; __shared__ float sb[32];
    int t = threadIdx.x;
    float v = (t < SSZ) ? g_scores[t] : -3e38f;
    int   i = (t < SSZ) ? t : 0x7FFFFFFF;
    bargmax(v, i, sv, si);
    int best = i;
    float c = out_s[(size_t)best * DIM + t];
    g_cand[t] = c;
    float n2 = bsum(c * c, sb);
    if (t == 0) g_candn2 = n2;
}

__global__ void k_mprep(const float* __restrict__ m) {
    int t = threadIdx.x;
    int w = (blockIdx.x * 256 + t) >> 5;
    int lane = t & 31;
    const float4* mr = (const float4*)(m + (size_t)w * DIM);
    float n2 = 0.f;
    float4 v0 = make_float4(0, 0, 0, 0);
#pragma unroll
    for (int k = 0; k < 8; k++) {
        float4 v = mr[lane + 32 * k];
        n2 += dot4(v, v);
        if (k == 0) v0 = v;
    }
    n2 = wsum(n2);
    float sp2 = (lane < 16) ? dot4(v0, v0) : 0.f;
    sp2 = wsum(sp2);
    float rinv = rsqrtf(n2);
    if (lane < 16) {
        float4 pv;
        pv.x = v0.x * rinv; pv.y = v0.y * rinv; pv.z = v0.z * rinv; pv.w = v0.w * rinv;
        ((float4*)(g_P + (size_t)w * PD))[lane] = pv;
    }
    if (!lane) {
        g_mn2[w] = n2;
        g_res[w] = sqrtf(fmaxf(0.f, 1.f - sp2 * rinv * rinv));
    }
}

__global__ void k_msims(const float* __restrict__ m) {
    __shared__ float4 scand[256];
    int t = threadIdx.x;
    scand[t] = ((const float4*)g_cand)[t];
    __syncthreads();
    int lane = t & 31;
    float rc = rsqrtf(g_candn2);
    for (int w = (blockIdx.x * 256 + t) >> 5; w < MSZ; w += (gridDim.x * 256) >> 5) {
        const float4* mr = (const float4*)(m + (size_t)w * DIM);
        float dc = 0.f;
#pragma unroll
        for (int k = 0; k < 8; k++) dc += dot4(mr[lane + 32 * k], scand[lane + 32 * k]);
        dc = wsum(dc);
        if (!lane) g_sims[w] = dc * rsqrtf(g_mn2[w]) * rc;
    }
}

__global__ void k_screen() {
    int k = blockIdx.x;
    int bi = (int)((sqrtf(8.f * (float)k + 1.f) - 1.f) * 0.5f);
    while ((bi + 1) * (bi + 2) / 2 <= k) bi++;
    while (bi * (bi + 1) / 2 > k) bi--;
    int bj = k - bi * (bi + 1) / 2;
    extern __shared__ float sm[];
    float* sPi = sm;
    float* sPj = sm + TB * LDP;
    __shared__ float sri[TB], srj[TB];
    int t = threadIdx.x;
    int i0 = bi * TB, j0 = bj * TB;
#pragma unroll
    for (int q = 0; q < 8; q++) {
        int id = t + 256 * q, row = id >> 4, col = (id & 15) * 4;
        *(float4*)&sPi[row * LDP + col] = *(const float4*)&g_P[(size_t)(i0 + row) * PD + col];
        *(float4*)&sPj[row * LDP + col] = *(const float4*)&g_P[(size_t)(j0 + row) * PD + col];
    }
    if (t < TB) { sri[t] = g_res[i0 + t]; srj[t] = g_res[j0 + t]; }
    __syncthreads();
    int tx = t & 15, ty = t >> 4;
    float acc[8][8];
#pragma unroll
    for (int a = 0; a < 8; a++)
#pragma unroll
        for (int b = 0; b < 8; b++) acc[a][b] = 0.f;
    for (int d = 0; d < PD; d += 4) {
        float4 A[8], B[8];
#pragma unroll
        for (int a = 0; a < 8; a++) A[a] = *(float4*)&sPi[(ty + 16 * a) * LDP + d];
#pragma unroll
        for (int b = 0; b < 8; b++) B[b] = *(float4*)&sPj[(tx + 16 * b) * LDP + d];
#pragma unroll
        for (int a = 0; a < 8; a++)
#pragma unroll
            for (int b = 0; b < 8; b++) acc[a][b] += dot4(A[a], B[b]);
    }
#pragma unroll
    for (int a = 0; a < 8; a++) {
        int i = i0 + ty + 16 * a;
#pragma unroll
        for (int b = 0; b < 8; b++) {
            int j = j0 + tx + 16 * b;
            if (i > j) {
                float bound = acc[a][b] + sri[ty + 16 * a] * srj[tx + 16 * b];
                if (bound > SCREEN_T) {
                    int p = atomicAdd(&g_npairs, 1);
                    if (p < PAIR_CAP) { g_pairs[2 * p] = i; g_pairs[2 * p + 1] = j; }
                }
            }
        }
    }
}

__global__ void k_exactbrute(const float* __restrict__ m) {
    __shared__ float sb[8];
    __shared__ unsigned long long bk_;
    int t = threadIdx.x, lane = t & 31, wid = t >> 5;
    int np = g_npairs;
    if (np <= PAIR_CAP) {
        for (int p = blockIdx.x; p < np; p += gridDim.x) {
            int i = g_pairs[2 * p], j = g_pairs[2 * p + 1];
            float s = dot4(((const float4*)(m + (size_t)i * DIM))[t],
                           ((const float4*)(m + (size_t)j * DIM))[t]);
            s = wsum(s);
            if (!lane) sb[wid] = s;
            __syncthreads();
            if (t == 0) {
                float tot = 0.f;
                for (int q = 0; q < 8; q++) tot += sb[q];
                float cosv = tot * rsqrtf(g_mn2[i] * g_mn2[j]);
                unsigned long long key =
                    ((unsigned long long)ordf(cosv) << 32) | (0xFFFFFFFFu - (unsigned)(i * MSZ + j));
                atomicMax(&g_intmax, key);
            }
            __syncthreads();
        }
    } else {
        if (t == 0) bk_ = 0ull;
        __syncthreads();
        for (int i = blockIdx.x; i < MSZ; i += gridDim.x) {
            if (i == 0) continue;
            float bc = -2.f; int bf = 0;
            for (int j = t; j < i; j += 256) {
                float s = 0.f;
                const float* mi = m + (size_t)i * DIM;
                const float* mj = m + (size_t)j * DIM;
                for (int e = 0; e < DIM; e++) s += mi[e] * mj[e];
                float c = s * rsqrtf(g_mn2[i] * g_mn2[j]);
                if (c > bc) { bc = c; bf = i * MSZ + j; }
            }
            unsigned long long key = ((unsigned long long)ordf(bc) << 32) | (0xFFFFFFFFu - (unsigned)bf);
            atomicMax(&bk_, key);
        }
        __syncthreads();
        if (t == 0) atomicMax(&g_intmax, bk_);
    }
}

__global__ void k_decide(const float* __restrict__ m, const float* __restrict__ mu,
                         float* __restrict__ out_m, float* __restrict__ out_mu) {
    __shared__ float sv[32]; __shared__ int si[32]; __shared__ float sb[32];
    __shared__ int s_any;
    int t = threadIdx.x;
    if (t == 0) s_any = 0;
    __syncthreads();
    float musum = 0.f, mn = 3e38f; int mni = 0x7FFFFFFF; int anyz = 0;
    for (int i = t; i < MSZ; i += 1024) {
        float u = mu[i];
        musum += u;
        if (u < mn) { mn = u; mni = i; }
        anyz |= (u == 0.f);
    }
    if (anyz) atomicOr(&s_any, 1);
    float mu_mean = bsum(musum, sb) / (float)MSZ;
    bargmin(mn, mni, sv, si);
    int li = mni;
    __syncthreads();
    int any0 = s_any;
    float smax = -3e38f; int smi = 0x7FFFFFFF;
    for (int i = t; i < MSZ; i += 1024) {
        float s = g_sims[i];
        if (s > smax || (s == smax && i < smi)) { smax = s; smi = i; }
    }
    bargmax(smax, smi, sv, si);
    int msi = smi; float simcand = smax;
    float cosint = -2.f; int i1 = 0, i2 = 0;
    if (g_npairs > 0) {
        unsigned long long kk = g_intmax;
        cosint = deordf((unsigned)(kk >> 32));
        unsigned fl = 0xFFFFFFFFu - (unsigned)(kk & 0xFFFFFFFFu);
        i1 = fl / MSZ; i2 = fl % MSZ;
    }
    if (any0) {
        out_m[(size_t)li * DIM + t] = g_cand[t];
        if (t == 0) out_mu[li] = mu_mean + 1e-5f;
    } else if (simcand > MERGE_T) {
        float merged = (m[(size_t)msi * DIM + t] + g_cand[t]) * 0.5f;
        float n2 = bsum(merged * merged, sb);
        float dn = fmaxf(sqrtf(n2), 1e-12f);
        out_m[(size_t)msi * DIM + t] = merged / dn;
        if (t == 0) out_mu[msi] = (mu[msi] + mu_mean) * 0.5f;
    } else if (cosint > MERGE_T) {
        float merged = (m[(size_t)i1 * DIM + t] + m[(size_t)i2 * DIM + t]) * 0.5f;
        float n2 = bsum(merged * merged, sb);
        float dn = fmaxf(sqrtf(n2), 1e-12f);
        out_m[(size_t)i1 * DIM + t] = merged / dn;
        out_m[(size_t)i2 * DIM + t] = g_cand[t];
        if (t == 0) {
            float nu1 = (mu[i1] + mu[i2]) * 0.5f;
            out_mu[i1] = nu1;
            float mean2 = mu_mean + (nu1 - mu[i1]) / (float)MSZ;
            out_mu[i2] = mean2 + 1e-5f;
        }
    } else {
        if (g_candn2 > g_mn2[li]) {
            out_m[(size_t)li * DIM + t] = g_cand[t];
            if (t == 0) out_mu[li] = mu_mean + 1e-5f;
        }
    }
}

__global__ void k_ltier(const float* __restrict__ l_in, const float* __restrict__ lu,
                        const int* __restrict__ sptr,
                        const float* __restrict__ out_m, const float* __restrict__ out_mu,
                        float* __restrict__ out_l, float* __restrict__ out_lu,
                        float* __restrict__ out_ptr) {
    __shared__ float sv[32]; __shared__ int si[32]; __shared__ float sb[32];
    int t = threadIdx.x;
    float mx = -3e38f; int mxi = 0x7FFFFFFF;
    for (int i = t; i < MSZ; i += 1024) {
        float u = out_mu[i];
        if (u > mx || (u == mx && i < mxi)) { mx = u; mxi = i; }
    }
    bargmax(mx, mxi, sv, si);
    int mi = mxi;
    float lsum = 0.f, lmn = 3e38f; int lmni = 0x7FFFFFFF;
    for (int i = t; i < LSZ; i += 1024) {
        float u = lu[i];
        lsum += u;
        if (u < lmn) { lmn = u; lmni = i; }
    }
    float ltot = bsum(lsum, sb);
    bargmin(lmn, lmni, sv, si);
    int lj = lmni;
    out_l[(size_t)lj * DIM + t] =
        0.9f * l_in[(size_t)lj * DIM + t] + 0.1f * out_m[(size_t)mi * DIM + t];
    if (t == 0) {
        out_lu[lj] = ltot / (float)LSZ;
        out_ptr[0] = (float)(((sptr[0] + KPROM) % SSZ + SSZ) % SSZ);
    }
}

// ------------- host -------------
extern "C" void kernel_launch(void* const* d_in, const int* in_sizes, int n_in,
                              void* d_out, int out_size) {
    const float* tok  = (const float*)d_in[0];
    const float* s_in = (const float*)d_in[1];
    const float* m_in = (const float*)d_in[2];
    const float* l_in = (const float*)d_in[3];
    const float* mu   = (const float*)d_in[4];
    const float* lu   = (const float*)d_in[5];
    const float* wq   = (const float*)d_in[6];
    const float* bq   = (const float*)d_in[7];
    const float* wk   = (const float*)d_in[8];
    const int*   sptr = (const int*)d_in[10];

    float* out    = (float*)d_out;
    float* out_s  = out;
    float* out_m  = out_s + (size_t)SSZ * DIM;
    float* out_l  = out_m + (size_t)MSZ * DIM;
    float* out_mu = out_l + (size_t)LSZ * DIM;
    float* out_lu = out_mu + MSZ;
    float* out_ptr = out_lu + LSZ;

    static cudaStream_t sA = 0, sB = 0, sC = 0;
    static cudaEvent_t evRoot = 0, evScopy = 0, evA = 0, evB = 0, evPrep = 0, evC = 0;
    if (!sA) {
        cudaStreamCreateWithFlags(&sA, cudaStreamNonBlocking);
        cudaStreamCreateWithFlags(&sB, cudaStreamNonBlocking);
        cudaStreamCreateWithFlags(&sC, cudaStreamNonBlocking);
        cudaEventCreateWithFlags(&evRoot, cudaEventDisableTiming);
        cudaEventCreateWithFlags(&evScopy, cudaEventDisableTiming);
        cudaEventCreateWithFlags(&evA, cudaEventDisableTiming);
        cudaEventCreateWithFlags(&evB, cudaEventDisableTiming);
        cudaEventCreateWithFlags(&evPrep, cudaEventDisableTiming);
        cudaEventCreateWithFlags(&evC, cudaEventDisableTiming);
        cudaFuncSetAttribute(k_screen, cudaFuncAttributeMaxDynamicSharedMemorySize,
                             2 * TB * LDP * sizeof(float));
    }

    k_init<<<1, 1>>>();
    cudaEventRecord(evRoot, 0);

    // branch A: output copies
    cudaStreamWaitEvent(sA, evRoot, 0);
    k_copy_small<<<512, 256, 0, sA>>>((const float4*)s_in, (float4*)out_s,
                                      (const float4*)mu, (float4*)out_mu,
                                      (const float4*)lu, (float4*)out_lu);
    cudaEventRecord(evScopy, sA);
    k_copy_m<<<2048, 256, 0, sA>>>((const float4*)m_in, (float4*)out_m);
    cudaEventRecord(evA, sA);

    // branch B: l copy+mean -> q -> v
    cudaStreamWaitEvent(sB, evRoot, 0);
    k_lmean1<<<dim3(DIM / 256, NLCHUNK), 256, 0, sB>>>(l_in, out_l);
    k_lmean2<<<DIM / 256, 256, 0, sB>>>();
    k_q<<<32, 1024, 0, sB>>>(wq, bq);
    k_v1<<<dim3(DIM / 256, NVCHUNK), 256, 0, sB>>>(wk);
    k_v2<<<1, 1024, 0, sB>>>();
    cudaEventRecord(evB, sB);

    // origin: mprep -> screen -> exact
    k_mprep<<<MSZ / 8, 256>>>(m_in);
    cudaEventRecord(evPrep, 0);
    k_screen<<<NTRI, 256, 2 * TB * LDP * sizeof(float)>>>();
    k_exactbrute<<<256, 256>>>(m_in);

    // branch C: token chain -> scores -> candidate -> sims
    cudaStreamWaitEvent(sC, evRoot, 0);
    k_toknorm<<<CANDN / 32, 1024, 0, sC>>>(tok);
    k_topk<<<1, 1024, 0, sC>>>();
    cudaStreamWaitEvent(sC, evScopy, 0);
    k_scatter<<<KPROM, 256, 0, sC>>>(tok, sptr, out_s);
    cudaStreamWaitEvent(sC, evB, 0);
    k_scores<<<SSZ / 32, 1024, 0, sC>>>(out_s);
    k_pickcand<<<1, 1024, 0, sC>>>(out_s);
    cudaStreamWaitEvent(sC, evPrep, 0);
    k_msims<<<128, 256, 0, sC>>>(m_in);
    cudaEventRecord(evC, sC);

    cudaStreamWaitEvent(0, evA, 0);
    cudaStreamWaitEvent(0, evC, 0);
    k_decide<<<1, 1024>>>(m_in, mu, out_m, out_mu);
    k_ltier<<<1, 1024>>>(l_in, lu, sptr, out_m, out_mu, out_l, out_lu, out_ptr);
}